// round 1
// baseline (speedup 1.0000x reference)
#include <cuda_runtime.h>
#include <cstddef>

// Problem constants
#define BV 4
#define HN 16
#define SV 1024
#define DV 64
#define BH (BV*HN)
constexpr float SCALE = 32.0f;   // sqrt(1024)

// Scratch for folded q'' = 32*q + Wd_h * (q @ W_h)   (16 MB, device global — no alloc)
__device__ float g_qp[(size_t)BH * SV * DV];

// ---------------------------------------------------------------------------
// Kernel 1: fold the bilinear weight into q.
//   q''[bh][i][e] = 32*q[i,e] + Wd[h] * sum_d q[i,d] * W[h][d][e]
// grid: (SV/64, BH), block: 256 threads
// ---------------------------------------------------------------------------
__global__ void fold_kernel(const float* __restrict__ q,
                            const float* __restrict__ W,
                            const float* __restrict__ Wd)
{
    const int bh   = blockIdx.y;
    const int h    = bh % HN;
    const int row0 = blockIdx.x * 64;

    const float* qb  = q    + (size_t)bh * SV * DV;
    float*       qpb = g_qp + (size_t)bh * SV * DV;
    const float* Wh  = W    + (size_t)h * DV * DV;
    const float  wd  = Wd[h];

    __shared__ float Ws[DV][DV];   // Ws[d][e]
    __shared__ float qs[64][DV];   // qs[i_local][d]

    const int t = threadIdx.x;     // 256 threads

    #pragma unroll
    for (int idx = t; idx < DV * DV; idx += 256)
        Ws[idx / DV][idx % DV] = Wh[idx];
    #pragma unroll
    for (int idx = t; idx < 64 * DV; idx += 256)
        qs[idx / DV][idx % DV] = qb[(size_t)row0 * DV + idx];
    __syncthreads();

    const int e    = t % 64;       // output column
    const int isub = t / 64;       // 0..3

    for (int ib = 0; ib < 64; ib += 4) {
        const int i = ib + isub;
        float acc = 0.0f;
        #pragma unroll
        for (int d = 0; d < DV; d++)
            acc = fmaf(qs[i][d], Ws[d][e], acc);
        qpb[(size_t)(row0 + i) * DV + e] = SCALE * qs[i][e] + wd * acc;
    }
}

// ---------------------------------------------------------------------------
// Kernel 2: batched GEMM  out[bh][i][j] = sum_e q''[i,e] * k[j,e] + Wd[h]*b[h]
// 128x128 block tile, K=64 resident in smem (transposed, padded), 8x8 microtile.
// grid: (SV/128, SV/128, BH) = (8, 8, 64), block: 256 threads
// ---------------------------------------------------------------------------
#define TPAD 132   // 128 + 4 pad: store bank = (4*d + row)%32 -> conflict-free,
                   // keeps float4 alignment for compute-side reads

__global__ __launch_bounds__(256, 2)
void score_kernel(const float* __restrict__ k,
                  const float* __restrict__ b,
                  const float* __restrict__ Wd,
                  float* __restrict__ out)
{
    extern __shared__ float smem[];
    float (*As)[TPAD] = (float (*)[TPAD])smem;                 // As[d][i_local]
    float (*Bs)[TPAD] = (float (*)[TPAD])(smem + 64 * TPAD);   // Bs[d][j_local]

    const int bh = blockIdx.z;
    const int h  = bh % HN;
    const float c = Wd[h] * b[h];

    const float* qp = g_qp + (size_t)bh * SV * DV;
    const float* kb = k    + (size_t)bh * SV * DV;
    float*       ob = out  + (size_t)bh * SV * SV;

    const int i0 = blockIdx.y * 128;
    const int j0 = blockIdx.x * 128;
    const int t  = threadIdx.x;

    // ---- Load both 128x64 tiles, transposed into smem ----
    // idx -> (row = idx%128, c4 = idx/128). Consecutive threads take
    // consecutive rows: smem stores are conflict-free; global reads hit L2.
    #pragma unroll
    for (int it = 0; it < 8; it++) {
        const int idx = t + it * 256;      // 0..2047
        const int row = idx & 127;
        const int c4  = idx >> 7;          // 0..15
        float4 va = *reinterpret_cast<const float4*>(&qp[(size_t)(i0 + row) * DV + c4 * 4]);
        As[c4 * 4 + 0][row] = va.x;
        As[c4 * 4 + 1][row] = va.y;
        As[c4 * 4 + 2][row] = va.z;
        As[c4 * 4 + 3][row] = va.w;
        float4 vb = *reinterpret_cast<const float4*>(&kb[(size_t)(j0 + row) * DV + c4 * 4]);
        Bs[c4 * 4 + 0][row] = vb.x;
        Bs[c4 * 4 + 1][row] = vb.y;
        Bs[c4 * 4 + 2][row] = vb.z;
        Bs[c4 * 4 + 3][row] = vb.w;
    }
    __syncthreads();

    // ---- Compute 8x8 per thread ----
    const int ty = t >> 4;   // 0..15 -> i groups
    const int tx = t & 15;   // 0..15 -> j groups
    // rows:  i0 + {ty*4..ty*4+3} and i0 + 64 + {ty*4..ty*4+3}
    // cols:  j0 + {tx*4..tx*4+3} and j0 + 64 + {tx*4..tx*4+3}

    float acc[8][8];
    #pragma unroll
    for (int x = 0; x < 8; x++)
        #pragma unroll
        for (int y = 0; y < 8; y++) acc[x][y] = 0.0f;

    #pragma unroll 8
    for (int d = 0; d < DV; d++) {
        float a[8], bb[8];
        *reinterpret_cast<float4*>(&a[0])  = *reinterpret_cast<const float4*>(&As[d][ty * 4]);
        *reinterpret_cast<float4*>(&a[4])  = *reinterpret_cast<const float4*>(&As[d][64 + ty * 4]);
        *reinterpret_cast<float4*>(&bb[0]) = *reinterpret_cast<const float4*>(&Bs[d][tx * 4]);
        *reinterpret_cast<float4*>(&bb[4]) = *reinterpret_cast<const float4*>(&Bs[d][64 + tx * 4]);
        #pragma unroll
        for (int x = 0; x < 8; x++)
            #pragma unroll
            for (int y = 0; y < 8; y++)
                acc[x][y] = fmaf(a[x], bb[y], acc[x][y]);
    }

    // ---- Epilogue: add bias, coalesced float4 stores ----
    #pragma unroll
    for (int g = 0; g < 2; g++) {
        #pragma unroll
        for (int r = 0; r < 4; r++) {
            const int x = g * 4 + r;
            const int i = i0 + g * 64 + ty * 4 + r;
            float* p = ob + (size_t)i * SV + j0;
            float4 v0 = make_float4(acc[x][0] + c, acc[x][1] + c,
                                    acc[x][2] + c, acc[x][3] + c);
            float4 v1 = make_float4(acc[x][4] + c, acc[x][5] + c,
                                    acc[x][6] + c, acc[x][7] + c);
            *reinterpret_cast<float4*>(p + tx * 4)      = v0;
            *reinterpret_cast<float4*>(p + 64 + tx * 4) = v1;
        }
    }
}

// ---------------------------------------------------------------------------
extern "C" void kernel_launch(void* const* d_in, const int* in_sizes, int n_in,
                              void* d_out, int out_size)
{
    const float* q  = (const float*)d_in[0];
    const float* k  = (const float*)d_in[1];
    const float* W  = (const float*)d_in[2];
    const float* b  = (const float*)d_in[3];
    const float* Wd = (const float*)d_in[4];
    float* out = (float*)d_out;

    // Dynamic smem for the GEMM kernel: 2 * 64 * 132 * 4 = 67584 B (> 48KB static)
    const int smem_bytes = 2 * 64 * TPAD * (int)sizeof(float);
    cudaFuncSetAttribute(score_kernel,
                         cudaFuncAttributeMaxDynamicSharedMemorySize, smem_bytes);

    dim3 g1(SV / 64, BH);
    fold_kernel<<<g1, 256>>>(q, W, Wd);

    dim3 g2(SV / 128, SV / 128, BH);
    score_kernel<<<g2, 256, smem_bytes>>>(k, b, Wd, out);
}

// round 3
// speedup vs baseline: 1.8027x; 1.8027x over previous
#include <cuda_runtime.h>
#include <cuda_bf16.h>
#include <cstdint>
#include <cstddef>

// Problem constants
#define BV 4
#define HN 16
#define SV 1024
#define DV 64
#define BH (BV*HN)
constexpr float SCALE = 32.0f;   // sqrt(1024)

// bf16 split operands (device scratch; no allocation)
__device__ __nv_bfloat16 g_qhi[(size_t)BH * SV * DV];
__device__ __nv_bfloat16 g_qlo[(size_t)BH * SV * DV];
__device__ __nv_bfloat16 g_khi[(size_t)BH * SV * DV];
__device__ __nv_bfloat16 g_klo[(size_t)BH * SV * DV];

__device__ __forceinline__ uint32_t smem_u32(const void* p) {
    uint32_t a;
    asm("{ .reg .u64 t; cvta.to.shared.u64 t, %1; cvt.u32.u64 %0, t; }" : "=r"(a) : "l"(p));
    return a;
}
__device__ __forceinline__ uint32_t sw128(uint32_t off) {
    return off ^ ((off >> 3) & 0x70);
}

// ---------------------------------------------------------------------------
// Kernel 1: fold bilinear into q, emit bf16 hi/lo split.
//   x = 32*q[i,e] + Wd[h] * sum_d q[i,d]*W[h][d][e];  hi=bf16(x), lo=bf16(x-hi)
// ---------------------------------------------------------------------------
__global__ void fold_kernel(const float* __restrict__ q,
                            const float* __restrict__ W,
                            const float* __restrict__ Wd)
{
    const int bh   = blockIdx.y;
    const int h    = bh % HN;
    const int row0 = blockIdx.x * 64;

    const float* qb = q + (size_t)bh * SV * DV;
    __nv_bfloat16* oh = g_qhi + (size_t)bh * SV * DV;
    __nv_bfloat16* ol = g_qlo + (size_t)bh * SV * DV;
    const float* Wh = W + (size_t)h * DV * DV;
    const float  wd = Wd[h];

    __shared__ float Ws[DV][DV];
    __shared__ float qs[64][DV];

    const int t = threadIdx.x;
    #pragma unroll
    for (int idx = t; idx < DV * DV; idx += 256)
        Ws[idx / DV][idx % DV] = Wh[idx];
    #pragma unroll
    for (int idx = t; idx < 64 * DV; idx += 256)
        qs[idx / DV][idx % DV] = qb[(size_t)row0 * DV + idx];
    __syncthreads();

    const int e    = t % 64;
    const int isub = t / 64;

    for (int ib = 0; ib < 64; ib += 4) {
        const int i = ib + isub;
        float acc = 0.0f;
        #pragma unroll
        for (int d = 0; d < DV; d++)
            acc = fmaf(qs[i][d], Ws[d][e], acc);
        float x = SCALE * qs[i][e] + wd * acc;
        __nv_bfloat16 hi = __float2bfloat16(x);
        float r = x - __bfloat162float(hi);
        oh[(size_t)(row0 + i) * DV + e] = hi;
        ol[(size_t)(row0 + i) * DV + e] = __float2bfloat16(r);
    }
}

// ---------------------------------------------------------------------------
// Kernel 2: split k into bf16 hi/lo. Grid-stride, float4 vectorized.
// ---------------------------------------------------------------------------
__global__ void ksplit_kernel(const float* __restrict__ k)
{
    const size_t n4 = (size_t)BH * SV * DV / 4;
    size_t i = (size_t)blockIdx.x * blockDim.x + threadIdx.x;
    if (i >= n4) return;
    float4 v = reinterpret_cast<const float4*>(k)[i];
    __nv_bfloat16 h0 = __float2bfloat16(v.x);
    __nv_bfloat16 h1 = __float2bfloat16(v.y);
    __nv_bfloat16 h2 = __float2bfloat16(v.z);
    __nv_bfloat16 h3 = __float2bfloat16(v.w);
    __nv_bfloat16 l0 = __float2bfloat16(v.x - __bfloat162float(h0));
    __nv_bfloat16 l1 = __float2bfloat16(v.y - __bfloat162float(h1));
    __nv_bfloat16 l2 = __float2bfloat16(v.z - __bfloat162float(h2));
    __nv_bfloat16 l3 = __float2bfloat16(v.w - __bfloat162float(h3));
    __nv_bfloat162* ph = reinterpret_cast<__nv_bfloat162*>(g_khi);
    __nv_bfloat162* pl = reinterpret_cast<__nv_bfloat162*>(g_klo);
    ph[2 * i]     = __nv_bfloat162(h0, h1);
    ph[2 * i + 1] = __nv_bfloat162(h2, h3);
    pl[2 * i]     = __nv_bfloat162(l0, l1);
    pl[2 * i + 1] = __nv_bfloat162(l2, l3);
}

// ---------------------------------------------------------------------------
// Kernel 3: batched GEMM on HMMA (mma.sync m16n8k16 bf16 -> f32).
//   out[bh][i][j] = q''_i · k_j + Wd[h]*b[h]    (2-term bf16 split, 3 passes)
// One 128x128 tile per CTA. grid (8,8,64), 256 threads = 8 warps.
// Warp tile: 32(M) x 64(N). K=64 in smem, SW128-swizzled, ldmatrix.x4.
// ---------------------------------------------------------------------------
#define TILE_B 16384
#define SMEM_NEED (4 * TILE_B + 1024)

__device__ __forceinline__ void ldsm_x4(uint32_t addr, uint32_t& r0, uint32_t& r1,
                                        uint32_t& r2, uint32_t& r3) {
    asm volatile("ldmatrix.sync.aligned.m8n8.x4.shared.b16 {%0,%1,%2,%3}, [%4];"
                 : "=r"(r0), "=r"(r1), "=r"(r2), "=r"(r3) : "r"(addr));
}
__device__ __forceinline__ void mma_bf16(float* c, const uint32_t* a,
                                         uint32_t b0, uint32_t b1) {
    asm volatile(
        "mma.sync.aligned.m16n8k16.row.col.f32.bf16.bf16.f32 "
        "{%0,%1,%2,%3}, {%4,%5,%6,%7}, {%8,%9}, {%0,%1,%2,%3};"
        : "+f"(c[0]), "+f"(c[1]), "+f"(c[2]), "+f"(c[3])
        : "r"(a[0]), "r"(a[1]), "r"(a[2]), "r"(a[3]), "r"(b0), "r"(b1));
}

__global__ __launch_bounds__(256, 2)
void score_mma_kernel(const float* __restrict__ b,
                      const float* __restrict__ Wd,
                      float* __restrict__ out)
{
    extern __shared__ char smem_raw[];
    const uint32_t smem_base = smem_u32(smem_raw);
    const uint32_t base_al   = (smem_base + 1023u) & ~1023u;
    char* tilec = smem_raw + (base_al - smem_base);

    const int t    = threadIdx.x;
    const int wid  = t >> 5;
    const int lane = t & 31;
    const int bh   = blockIdx.z;
    const int h    = bh % HN;
    const int i0   = blockIdx.y * 128;
    const int j0   = blockIdx.x * 128;

    // ---- Load 4 operand tiles (A_hi, A_lo, B_hi, B_lo) into swizzled smem ----
    const size_t boff = (size_t)bh * SV * DV;
    const __nv_bfloat16* qh = g_qhi + boff + (size_t)i0 * DV;
    const __nv_bfloat16* ql = g_qlo + boff + (size_t)i0 * DV;
    const __nv_bfloat16* kh = g_khi + boff + (size_t)j0 * DV;
    const __nv_bfloat16* kl = g_klo + boff + (size_t)j0 * DV;

    #pragma unroll
    for (int it = 0; it < 4; it++) {
        const int idx = t + it * 256;      // 0..1023
        const int row = idx >> 3;
        const int c16 = idx & 7;
        const uint32_t off = sw128((uint32_t)(row * 128 + c16 * 16));
        *reinterpret_cast<uint4*>(tilec + off) =
            reinterpret_cast<const uint4*>(qh + (size_t)row * DV)[c16];
        *reinterpret_cast<uint4*>(tilec + TILE_B + off) =
            reinterpret_cast<const uint4*>(ql + (size_t)row * DV)[c16];
        *reinterpret_cast<uint4*>(tilec + 2 * TILE_B + off) =
            reinterpret_cast<const uint4*>(kh + (size_t)row * DV)[c16];
        *reinterpret_cast<uint4*>(tilec + 3 * TILE_B + off) =
            reinterpret_cast<const uint4*>(kl + (size_t)row * DV)[c16];
    }
    __syncthreads();

    // ---- Per-warp MMA: warp (mw, nw) owns rows mw*32..+31, cols nw*64..+63 ----
    const int mw  = wid & 3;
    const int nw  = wid >> 2;
    const int m0w = mw * 32;
    const int n0w = nw * 64;

    float acc[2][8][4];
    #pragma unroll
    for (int m = 0; m < 2; m++)
        #pragma unroll
        for (int n = 0; n < 8; n++)
            #pragma unroll
            for (int r = 0; r < 4; r++) acc[m][n][r] = 0.0f;

    // ldmatrix lane address components
    const uint32_t a_row = lane & 15;
    const uint32_t a_ch  = (lane >> 4) << 4;                       // 0 or 16 bytes (k+8)
    const uint32_t b_row = (lane & 7) | ((lane >> 4) << 3);        // n within 16
    const uint32_t b_ch  = ((lane >> 3) & 1) << 4;                 // 0 or 16 bytes (k+8)

    // passes: (Ahi,Bhi), (Ahi,Blo), (Alo,Bhi)
    const uint32_t abase[3] = { base_al,              base_al,              base_al + TILE_B };
    const uint32_t bbase[3] = { base_al + 2 * TILE_B, base_al + 3 * TILE_B, base_al + 2 * TILE_B };

    #pragma unroll
    for (int p = 0; p < 3; p++) {
        const uint32_t Ab = abase[p];
        const uint32_t Bb = bbase[p];
        #pragma unroll
        for (int k = 0; k < 4; k++) {
            const uint32_t kb = (uint32_t)k * 32;
            uint32_t a[2][4];
            #pragma unroll
            for (int m = 0; m < 2; m++) {
                uint32_t addr = Ab + sw128((uint32_t)(m0w + m * 16 + a_row) * 128 + kb + a_ch);
                ldsm_x4(addr, a[m][0], a[m][1], a[m][2], a[m][3]);
            }
            uint32_t bf[8][2];
            #pragma unroll
            for (int tn = 0; tn < 4; tn++) {
                uint32_t addr = Bb + sw128((uint32_t)(n0w + tn * 16 + b_row) * 128 + kb + b_ch);
                ldsm_x4(addr, bf[2 * tn][0], bf[2 * tn][1], bf[2 * tn + 1][0], bf[2 * tn + 1][1]);
            }
            #pragma unroll
            for (int m = 0; m < 2; m++)
                #pragma unroll
                for (int n = 0; n < 8; n++)
                    mma_bf16(acc[m][n], a[m], bf[n][0], bf[n][1]);
        }
    }

    // ---- Epilogue: add bias, direct float2 stores (C frag layout) ----
    const float cbias = Wd[h] * b[h];
    float* ob = out + (size_t)bh * SV * SV;
    const int row_base = i0 + m0w + (lane >> 2);
    const int col_base = j0 + n0w + (lane & 3) * 2;

    #pragma unroll
    for (int m = 0; m < 2; m++) {
        #pragma unroll
        for (int half = 0; half < 2; half++) {
            const int r = row_base + m * 16 + half * 8;
            float* prow = ob + (size_t)r * SV + col_base;
            #pragma unroll
            for (int n = 0; n < 8; n++) {
                float2 v;
                v.x = acc[m][n][half * 2 + 0] + cbias;
                v.y = acc[m][n][half * 2 + 1] + cbias;
                *reinterpret_cast<float2*>(prow + n * 8) = v;
            }
        }
    }
}

// ---------------------------------------------------------------------------
extern "C" void kernel_launch(void* const* d_in, const int* in_sizes, int n_in,
                              void* d_out, int out_size)
{
    const float* q  = (const float*)d_in[0];
    const float* k  = (const float*)d_in[1];
    const float* W  = (const float*)d_in[2];
    const float* b  = (const float*)d_in[3];
    const float* Wd = (const float*)d_in[4];
    float* out = (float*)d_out;

    cudaFuncSetAttribute(score_mma_kernel,
                         cudaFuncAttributeMaxDynamicSharedMemorySize, SMEM_NEED);

    dim3 g1(SV / 64, BH);
    fold_kernel<<<g1, 256>>>(q, W, Wd);

    const size_t n4 = (size_t)BH * SV * DV / 4;
    ksplit_kernel<<<(unsigned)((n4 + 255) / 256), 256>>>(k);

    dim3 g3(SV / 128, SV / 128, BH);
    score_mma_kernel<<<g3, 256, SMEM_NEED>>>(b, Wd, out);
}

// round 4
// speedup vs baseline: 2.2363x; 1.2405x over previous
#include <cuda_runtime.h>
#include <cuda_fp16.h>
#include <cstdint>
#include <cstddef>

// Problem constants
#define BV 4
#define HN 16
#define SV 1024
#define DV 64
#define BH (BV*HN)
constexpr float SCALE = 32.0f;   // sqrt(1024)

// fp16 operands (device scratch; no allocation)
__device__ __half g_qhi[(size_t)BH * SV * DV];
__device__ __half g_khi[(size_t)BH * SV * DV];
__device__ __half g_klo[(size_t)BH * SV * DV];

__device__ __forceinline__ uint32_t smem_u32(const void* p) {
    uint32_t a;
    asm("{ .reg .u64 t; cvta.to.shared.u64 t, %1; cvt.u32.u64 %0, t; }" : "=r"(a) : "l"(p));
    return a;
}
__device__ __forceinline__ uint32_t sw128(uint32_t off) {
    return off ^ ((off >> 3) & 0x70);
}

// ---------------------------------------------------------------------------
// Kernel 1: fold bilinear into q, emit fp16.
//   x = 32*q[i,e] + Wd[h] * sum_d q[i,d]*W[h][d][e];  out = fp16(x)
// grid (SV/64, BH), 256 threads. Ws column in registers, 4-way ILP chains.
// ---------------------------------------------------------------------------
__global__ __launch_bounds__(256, 2)
void fold_kernel(const float* __restrict__ q,
                 const float* __restrict__ W,
                 const float* __restrict__ Wd)
{
    const int bh   = blockIdx.y;
    const int h    = bh % HN;
    const int row0 = blockIdx.x * 64;

    const float* qb = q + (size_t)bh * SV * DV + (size_t)row0 * DV;
    __half*      oh = g_qhi + (size_t)bh * SV * DV + (size_t)row0 * DV;
    const float* Wh = W + (size_t)h * DV * DV;
    const float  wd = Wd[h];

    __shared__ float qs[64][DV];

    const int t = threadIdx.x;
    const int e    = t % 64;          // output column (uniform mapping)
    const int isub = t / 64;          // 0..3 (uniform within a warp)

    // Ws column e -> registers (coalesced 128B per load across the warp)
    float wreg[64];
    #pragma unroll
    for (int d = 0; d < 64; d++)
        wreg[d] = Wh[d * 64 + e];

    // stage q tile (64x64 f32) as float4
    #pragma unroll
    for (int it = 0; it < 4; it++) {
        const int idx = t + it * 256;
        reinterpret_cast<float4*>(&qs[0][0])[idx] =
            reinterpret_cast<const float4*>(qb)[idx];
    }
    __syncthreads();

    // 16 rows per thread, processed as 4 groups of 4 concurrent chains
    #pragma unroll
    for (int jb = 0; jb < 4; jb++) {
        const int ib = isub * 16 + jb * 4;
        float a0 = 0.f, a1 = 0.f, a2 = 0.f, a3 = 0.f;
        #pragma unroll
        for (int d4 = 0; d4 < 16; d4++) {
            float4 q0 = *reinterpret_cast<const float4*>(&qs[ib + 0][d4 * 4]);
            float4 q1 = *reinterpret_cast<const float4*>(&qs[ib + 1][d4 * 4]);
            float4 q2 = *reinterpret_cast<const float4*>(&qs[ib + 2][d4 * 4]);
            float4 q3 = *reinterpret_cast<const float4*>(&qs[ib + 3][d4 * 4]);
            const float w0 = wreg[d4 * 4 + 0];
            const float w1 = wreg[d4 * 4 + 1];
            const float w2 = wreg[d4 * 4 + 2];
            const float w3 = wreg[d4 * 4 + 3];
            a0 = fmaf(q0.x, w0, a0); a0 = fmaf(q0.y, w1, a0);
            a0 = fmaf(q0.z, w2, a0); a0 = fmaf(q0.w, w3, a0);
            a1 = fmaf(q1.x, w0, a1); a1 = fmaf(q1.y, w1, a1);
            a1 = fmaf(q1.z, w2, a1); a1 = fmaf(q1.w, w3, a1);
            a2 = fmaf(q2.x, w0, a2); a2 = fmaf(q2.y, w1, a2);
            a2 = fmaf(q2.z, w2, a2); a2 = fmaf(q2.w, w3, a2);
            a3 = fmaf(q3.x, w0, a3); a3 = fmaf(q3.y, w1, a3);
            a3 = fmaf(q3.z, w2, a3); a3 = fmaf(q3.w, w3, a3);
        }
        oh[(ib + 0) * DV + e] = __float2half(SCALE * qs[ib + 0][e] + wd * a0);
        oh[(ib + 1) * DV + e] = __float2half(SCALE * qs[ib + 1][e] + wd * a1);
        oh[(ib + 2) * DV + e] = __float2half(SCALE * qs[ib + 2][e] + wd * a2);
        oh[(ib + 3) * DV + e] = __float2half(SCALE * qs[ib + 3][e] + wd * a3);
    }
}

// ---------------------------------------------------------------------------
// Kernel 2: split k into fp16 hi/lo. Grid-stride, float4 vectorized.
// ---------------------------------------------------------------------------
__global__ void ksplit_kernel(const float* __restrict__ k)
{
    const size_t n4 = (size_t)BH * SV * DV / 4;
    size_t i = (size_t)blockIdx.x * blockDim.x + threadIdx.x;
    if (i >= n4) return;
    float4 v = reinterpret_cast<const float4*>(k)[i];
    __half h0 = __float2half(v.x);
    __half h1 = __float2half(v.y);
    __half h2 = __float2half(v.z);
    __half h3 = __float2half(v.w);
    __half l0 = __float2half(v.x - __half2float(h0));
    __half l1 = __float2half(v.y - __half2float(h1));
    __half l2 = __float2half(v.z - __half2float(h2));
    __half l3 = __float2half(v.w - __half2float(h3));
    __half2* ph = reinterpret_cast<__half2*>(g_khi);
    __half2* pl = reinterpret_cast<__half2*>(g_klo);
    ph[2 * i]     = __half2(h0, h1);
    ph[2 * i + 1] = __half2(h2, h3);
    pl[2 * i]     = __half2(l0, l1);
    pl[2 * i + 1] = __half2(l2, l3);
}

// ---------------------------------------------------------------------------
// Kernel 3: batched GEMM on HMMA (mma.sync m16n8k16 fp16 -> f32), 2 passes:
//   D = Ahi*Bhi + Ahi*Blo ; A fragments reused across passes.
// One 128x128 tile per CTA. grid (8,8,64), 256 threads = 8 warps.
// Warp tile: 32(M) x 64(N). K=64 in smem, SW128-swizzled, ldmatrix.x4.
// ---------------------------------------------------------------------------
#define TILE_B 16384
#define SMEM_NEED (3 * TILE_B + 1024)

__device__ __forceinline__ void ldsm_x4(uint32_t addr, uint32_t& r0, uint32_t& r1,
                                        uint32_t& r2, uint32_t& r3) {
    asm volatile("ldmatrix.sync.aligned.m8n8.x4.shared.b16 {%0,%1,%2,%3}, [%4];"
                 : "=r"(r0), "=r"(r1), "=r"(r2), "=r"(r3) : "r"(addr));
}
__device__ __forceinline__ void mma_f16(float* c, const uint32_t* a,
                                        uint32_t b0, uint32_t b1) {
    asm volatile(
        "mma.sync.aligned.m16n8k16.row.col.f32.f16.f16.f32 "
        "{%0,%1,%2,%3}, {%4,%5,%6,%7}, {%8,%9}, {%0,%1,%2,%3};"
        : "+f"(c[0]), "+f"(c[1]), "+f"(c[2]), "+f"(c[3])
        : "r"(a[0]), "r"(a[1]), "r"(a[2]), "r"(a[3]), "r"(b0), "r"(b1));
}

__global__ __launch_bounds__(256, 2)
void score_mma_kernel(const float* __restrict__ b,
                      const float* __restrict__ Wd,
                      float* __restrict__ out)
{
    extern __shared__ char smem_raw[];
    const uint32_t smem_base = smem_u32(smem_raw);
    const uint32_t base_al   = (smem_base + 1023u) & ~1023u;
    char* tilec = smem_raw + (base_al - smem_base);

    const int t    = threadIdx.x;
    const int wid  = t >> 5;
    const int lane = t & 31;
    const int bh   = blockIdx.z;
    const int h    = bh % HN;
    const int i0   = blockIdx.y * 128;
    const int j0   = blockIdx.x * 128;

    // ---- Load 3 operand tiles (A, B_hi, B_lo) into swizzled smem ----
    const size_t boff = (size_t)bh * SV * DV;
    const __half* qh = g_qhi + boff + (size_t)i0 * DV;
    const __half* kh = g_khi + boff + (size_t)j0 * DV;
    const __half* kl = g_klo + boff + (size_t)j0 * DV;

    #pragma unroll
    for (int it = 0; it < 4; it++) {
        const int idx = t + it * 256;      // 0..1023
        const int row = idx >> 3;
        const int c16 = idx & 7;
        const uint32_t off = sw128((uint32_t)(row * 128 + c16 * 16));
        *reinterpret_cast<uint4*>(tilec + off) =
            reinterpret_cast<const uint4*>(qh + (size_t)row * DV)[c16];
        *reinterpret_cast<uint4*>(tilec + TILE_B + off) =
            reinterpret_cast<const uint4*>(kh + (size_t)row * DV)[c16];
        *reinterpret_cast<uint4*>(tilec + 2 * TILE_B + off) =
            reinterpret_cast<const uint4*>(kl + (size_t)row * DV)[c16];
    }
    __syncthreads();

    // ---- Per-warp MMA: warp (mw, nw) owns rows mw*32..+31, cols nw*64..+63 ----
    const int mw  = wid & 3;
    const int nw  = wid >> 2;
    const int m0w = mw * 32;
    const int n0w = nw * 64;

    float acc[2][8][4];
    #pragma unroll
    for (int m = 0; m < 2; m++)
        #pragma unroll
        for (int n = 0; n < 8; n++)
            #pragma unroll
            for (int r = 0; r < 4; r++) acc[m][n][r] = 0.0f;

    // ldmatrix lane address components
    const uint32_t a_row = lane & 15;
    const uint32_t a_ch  = (lane >> 4) << 4;                  // 0 or 16 bytes (k+8)
    const uint32_t b_row = (lane & 7) | ((lane >> 4) << 3);   // n within 16
    const uint32_t b_ch  = ((lane >> 3) & 1) << 4;            // 0 or 16 bytes (k+8)

    const uint32_t Ab  = base_al;
    const uint32_t Bhb = base_al + TILE_B;
    const uint32_t Blb = base_al + 2 * TILE_B;

    #pragma unroll
    for (int k = 0; k < 4; k++) {
        const uint32_t kb = (uint32_t)k * 32;
        uint32_t a[2][4];
        #pragma unroll
        for (int m = 0; m < 2; m++) {
            uint32_t addr = Ab + sw128((uint32_t)(m0w + m * 16 + a_row) * 128 + kb + a_ch);
            ldsm_x4(addr, a[m][0], a[m][1], a[m][2], a[m][3]);
        }
        uint32_t bhf[8][2], blf[8][2];
        #pragma unroll
        for (int tn = 0; tn < 4; tn++) {
            uint32_t rowoff = (uint32_t)(n0w + tn * 16 + b_row) * 128 + kb + b_ch;
            uint32_t sw = sw128(rowoff);
            ldsm_x4(Bhb + sw, bhf[2 * tn][0], bhf[2 * tn][1], bhf[2 * tn + 1][0], bhf[2 * tn + 1][1]);
            ldsm_x4(Blb + sw, blf[2 * tn][0], blf[2 * tn][1], blf[2 * tn + 1][0], blf[2 * tn + 1][1]);
        }
        #pragma unroll
        for (int m = 0; m < 2; m++)
            #pragma unroll
            for (int n = 0; n < 8; n++) {
                mma_f16(acc[m][n], a[m], bhf[n][0], bhf[n][1]);
                mma_f16(acc[m][n], a[m], blf[n][0], blf[n][1]);
            }
    }

    // ---- Epilogue: add bias, direct float2 stores (C frag layout) ----
    const float cbias = Wd[h] * b[h];
    float* ob = out + (size_t)bh * SV * SV;
    const int row_base = i0 + m0w + (lane >> 2);
    const int col_base = j0 + n0w + (lane & 3) * 2;

    #pragma unroll
    for (int m = 0; m < 2; m++) {
        #pragma unroll
        for (int half = 0; half < 2; half++) {
            const int r = row_base + m * 16 + half * 8;
            float* prow = ob + (size_t)r * SV + col_base;
            #pragma unroll
            for (int n = 0; n < 8; n++) {
                float2 v;
                v.x = acc[m][n][half * 2 + 0] + cbias;
                v.y = acc[m][n][half * 2 + 1] + cbias;
                *reinterpret_cast<float2*>(prow + n * 8) = v;
            }
        }
    }
}

// ---------------------------------------------------------------------------
extern "C" void kernel_launch(void* const* d_in, const int* in_sizes, int n_in,
                              void* d_out, int out_size)
{
    const float* q  = (const float*)d_in[0];
    const float* k  = (const float*)d_in[1];
    const float* W  = (const float*)d_in[2];
    const float* b  = (const float*)d_in[3];
    const float* Wd = (const float*)d_in[4];
    float* out = (float*)d_out;

    cudaFuncSetAttribute(score_mma_kernel,
                         cudaFuncAttributeMaxDynamicSharedMemorySize, SMEM_NEED);

    dim3 g1(SV / 64, BH);
    fold_kernel<<<g1, 256>>>(q, W, Wd);

    const size_t n4 = (size_t)BH * SV * DV / 4;
    ksplit_kernel<<<(unsigned)((n4 + 255) / 256), 256>>>(k);

    dim3 g3(SV / 128, SV / 128, BH);
    score_mma_kernel<<<g3, 256, SMEM_NEED>>>(b, Wd, out);
}

// round 5
// speedup vs baseline: 2.4120x; 1.0785x over previous
#include <cuda_runtime.h>
#include <cuda_fp16.h>
#include <cstdint>
#include <cstddef>

// Problem constants
#define BV 4
#define HN 16
#define SV 1024
#define DV 64
#define BH (BV*HN)
constexpr float SCALE = 32.0f;   // sqrt(1024)

// fp16 operands (device scratch; no allocation)
__device__ __half g_qhi[(size_t)BH * SV * DV];
__device__ __half g_khi[(size_t)BH * SV * DV];

__device__ __forceinline__ uint32_t smem_u32(const void* p) {
    uint32_t a;
    asm("{ .reg .u64 t; cvta.to.shared.u64 t, %1; cvt.u32.u64 %0, t; }" : "=r"(a) : "l"(p));
    return a;
}
__device__ __forceinline__ uint32_t sw128(uint32_t off) {
    return off ^ ((off >> 3) & 0x70);
}

// ---------------------------------------------------------------------------
// Kernel 1 (fused prep):
//  blocks with blockIdx.y <  BH : fold bilinear into q, emit fp16
//      x = 32*q[i,e] + Wd[h] * sum_d q[i,d]*W[h][d][e];  g_qhi = fp16(x)
//  blocks with blockIdx.y >= BH : convert k -> fp16 (g_khi)
// grid (16, BH+8), 512 threads.
// ---------------------------------------------------------------------------
#define KCONV_BLKS_Y 8
#define KCONV_TOTAL  (16 * KCONV_BLKS_Y)          // 128 blocks
__global__ __launch_bounds__(512, 1)
void prep_kernel(const float* __restrict__ q,
                 const float* __restrict__ k,
                 const float* __restrict__ W,
                 const float* __restrict__ Wd)
{
    const int t = threadIdx.x;

    if (blockIdx.y >= BH) {
        // ---- k -> fp16 conversion ----
        const int pb = (blockIdx.y - BH) * gridDim.x + blockIdx.x;   // 0..127
        const size_t n4      = (size_t)BH * SV * DV / 4;             // 1M float4
        const size_t per_blk = n4 / KCONV_TOTAL;                     // 8192
        const size_t base    = (size_t)pb * per_blk;
        __half2* ph = reinterpret_cast<__half2*>(g_khi);
        #pragma unroll
        for (int it = 0; it < (int)(8192 / 512); it++) {
            const size_t i = base + (size_t)it * 512 + t;
            float4 v = reinterpret_cast<const float4*>(k)[i];
            ph[2 * i]     = __floats2half2_rn(v.x, v.y);
            ph[2 * i + 1] = __floats2half2_rn(v.z, v.w);
        }
        return;
    }

    // ---- fold ----
    const int bh   = blockIdx.y;
    const int h    = bh % HN;
    const int row0 = blockIdx.x * 64;

    const float* qb = q + (size_t)bh * SV * DV + (size_t)row0 * DV;
    __half*      oh = g_qhi + (size_t)bh * SV * DV + (size_t)row0 * DV;
    const float* Wh = W + (size_t)h * DV * DV;
    const float  wd = Wd[h];

    __shared__ float qs[64][DV];

    const int e    = t & 63;      // output column
    const int isub = t >> 6;      // 0..7

    // Ws column e -> registers (coalesced across the warp)
    float wreg[64];
    #pragma unroll
    for (int d = 0; d < 64; d++)
        wreg[d] = Wh[d * 64 + e];

    // stage q tile (64x64 f32) as float4
    #pragma unroll
    for (int it = 0; it < 2; it++) {
        const int idx = t + it * 512;
        reinterpret_cast<float4*>(&qs[0][0])[idx] =
            reinterpret_cast<const float4*>(qb)[idx];
    }
    __syncthreads();

    // 8 rows per thread: 2 groups of 4 concurrent FMA chains
    #pragma unroll
    for (int jb = 0; jb < 2; jb++) {
        const int ib = isub * 8 + jb * 4;
        float a0 = 0.f, a1 = 0.f, a2 = 0.f, a3 = 0.f;
        #pragma unroll
        for (int d4 = 0; d4 < 16; d4++) {
            float4 q0 = *reinterpret_cast<const float4*>(&qs[ib + 0][d4 * 4]);
            float4 q1 = *reinterpret_cast<const float4*>(&qs[ib + 1][d4 * 4]);
            float4 q2 = *reinterpret_cast<const float4*>(&qs[ib + 2][d4 * 4]);
            float4 q3 = *reinterpret_cast<const float4*>(&qs[ib + 3][d4 * 4]);
            const float w0 = wreg[d4 * 4 + 0];
            const float w1 = wreg[d4 * 4 + 1];
            const float w2 = wreg[d4 * 4 + 2];
            const float w3 = wreg[d4 * 4 + 3];
            a0 = fmaf(q0.x, w0, a0); a0 = fmaf(q0.y, w1, a0);
            a0 = fmaf(q0.z, w2, a0); a0 = fmaf(q0.w, w3, a0);
            a1 = fmaf(q1.x, w0, a1); a1 = fmaf(q1.y, w1, a1);
            a1 = fmaf(q1.z, w2, a1); a1 = fmaf(q1.w, w3, a1);
            a2 = fmaf(q2.x, w0, a2); a2 = fmaf(q2.y, w1, a2);
            a2 = fmaf(q2.z, w2, a2); a2 = fmaf(q2.w, w3, a2);
            a3 = fmaf(q3.x, w0, a3); a3 = fmaf(q3.y, w1, a3);
            a3 = fmaf(q3.z, w2, a3); a3 = fmaf(q3.w, w3, a3);
        }
        oh[(ib + 0) * DV + e] = __float2half(SCALE * qs[ib + 0][e] + wd * a0);
        oh[(ib + 1) * DV + e] = __float2half(SCALE * qs[ib + 1][e] + wd * a1);
        oh[(ib + 2) * DV + e] = __float2half(SCALE * qs[ib + 2][e] + wd * a2);
        oh[(ib + 3) * DV + e] = __float2half(SCALE * qs[ib + 3][e] + wd * a3);
    }
}

// ---------------------------------------------------------------------------
// Kernel 2: batched GEMM on HMMA (mma.sync m16n8k16 fp16 -> f32), single pass.
//   out[bh][i][j] = q''_i · k_j + Wd[h]*b[h]
// One 128x128 tile per CTA. grid (8,8,64), 256 threads = 8 warps.
// Warp tile: 32(M) x 64(N). K=64 in smem, SW128-swizzled, ldmatrix.x4.
// ---------------------------------------------------------------------------
#define TILE_B 16384
#define SMEM_NEED (2 * TILE_B + 1024)

__device__ __forceinline__ void ldsm_x4(uint32_t addr, uint32_t& r0, uint32_t& r1,
                                        uint32_t& r2, uint32_t& r3) {
    asm volatile("ldmatrix.sync.aligned.m8n8.x4.shared.b16 {%0,%1,%2,%3}, [%4];"
                 : "=r"(r0), "=r"(r1), "=r"(r2), "=r"(r3) : "r"(addr));
}
__device__ __forceinline__ void mma_f16(float* c, const uint32_t* a,
                                        uint32_t b0, uint32_t b1) {
    asm volatile(
        "mma.sync.aligned.m16n8k16.row.col.f32.f16.f16.f32 "
        "{%0,%1,%2,%3}, {%4,%5,%6,%7}, {%8,%9}, {%0,%1,%2,%3};"
        : "+f"(c[0]), "+f"(c[1]), "+f"(c[2]), "+f"(c[3])
        : "r"(a[0]), "r"(a[1]), "r"(a[2]), "r"(a[3]), "r"(b0), "r"(b1));
}

__global__ __launch_bounds__(256, 2)
void score_mma_kernel(const float* __restrict__ b,
                      const float* __restrict__ Wd,
                      float* __restrict__ out)
{
    extern __shared__ char smem_raw[];
    const uint32_t smem_base = smem_u32(smem_raw);
    const uint32_t base_al   = (smem_base + 1023u) & ~1023u;
    char* tilec = smem_raw + (base_al - smem_base);

    const int t    = threadIdx.x;
    const int wid  = t >> 5;
    const int lane = t & 31;
    const int bh   = blockIdx.z;
    const int h    = bh % HN;
    const int i0   = blockIdx.y * 128;
    const int j0   = blockIdx.x * 128;

    // ---- Load 2 operand tiles (A, B) into swizzled smem ----
    const size_t boff = (size_t)bh * SV * DV;
    const __half* qh = g_qhi + boff + (size_t)i0 * DV;
    const __half* kh = g_khi + boff + (size_t)j0 * DV;

    #pragma unroll
    for (int it = 0; it < 4; it++) {
        const int idx = t + it * 256;      // 0..1023
        const int row = idx >> 3;
        const int c16 = idx & 7;
        const uint32_t off = sw128((uint32_t)(row * 128 + c16 * 16));
        *reinterpret_cast<uint4*>(tilec + off) =
            reinterpret_cast<const uint4*>(qh + (size_t)row * DV)[c16];
        *reinterpret_cast<uint4*>(tilec + TILE_B + off) =
            reinterpret_cast<const uint4*>(kh + (size_t)row * DV)[c16];
    }
    __syncthreads();

    // ---- Per-warp MMA: warp (mw, nw) owns rows mw*32..+31, cols nw*64..+63 ----
    const int mw  = wid & 3;
    const int nw  = wid >> 2;
    const int m0w = mw * 32;
    const int n0w = nw * 64;

    float acc[2][8][4];
    #pragma unroll
    for (int m = 0; m < 2; m++)
        #pragma unroll
        for (int n = 0; n < 8; n++)
            #pragma unroll
            for (int r = 0; r < 4; r++) acc[m][n][r] = 0.0f;

    // ldmatrix lane address components
    const uint32_t a_row = lane & 15;
    const uint32_t a_ch  = (lane >> 4) << 4;                  // 0 or 16 bytes (k+8)
    const uint32_t b_row = (lane & 7) | ((lane >> 4) << 3);   // n within 16
    const uint32_t b_ch  = ((lane >> 3) & 1) << 4;            // 0 or 16 bytes (k+8)

    const uint32_t Ab = base_al;
    const uint32_t Bb = base_al + TILE_B;

    #pragma unroll
    for (int k = 0; k < 4; k++) {
        const uint32_t kb = (uint32_t)k * 32;
        uint32_t a[2][4];
        #pragma unroll
        for (int m = 0; m < 2; m++) {
            uint32_t addr = Ab + sw128((uint32_t)(m0w + m * 16 + a_row) * 128 + kb + a_ch);
            ldsm_x4(addr, a[m][0], a[m][1], a[m][2], a[m][3]);
        }
        uint32_t bf[8][2];
        #pragma unroll
        for (int tn = 0; tn < 4; tn++) {
            uint32_t addr = Bb + sw128((uint32_t)(n0w + tn * 16 + b_row) * 128 + kb + b_ch);
            ldsm_x4(addr, bf[2 * tn][0], bf[2 * tn][1], bf[2 * tn + 1][0], bf[2 * tn + 1][1]);
        }
        #pragma unroll
        for (int m = 0; m < 2; m++)
            #pragma unroll
            for (int n = 0; n < 8; n++)
                mma_f16(acc[m][n], a[m], bf[n][0], bf[n][1]);
    }

    // ---- Epilogue: add bias, direct float2 stores (C frag layout) ----
    const float cbias = Wd[h] * b[h];
    float* ob = out + (size_t)bh * SV * SV;
    const int row_base = i0 + m0w + (lane >> 2);
    const int col_base = j0 + n0w + (lane & 3) * 2;

    #pragma unroll
    for (int m = 0; m < 2; m++) {
        #pragma unroll
        for (int half = 0; half < 2; half++) {
            const int r = row_base + m * 16 + half * 8;
            float* prow = ob + (size_t)r * SV + col_base;
            #pragma unroll
            for (int n = 0; n < 8; n++) {
                float2 v;
                v.x = acc[m][n][half * 2 + 0] + cbias;
                v.y = acc[m][n][half * 2 + 1] + cbias;
                *reinterpret_cast<float2*>(prow + n * 8) = v;
            }
        }
    }
}

// ---------------------------------------------------------------------------
extern "C" void kernel_launch(void* const* d_in, const int* in_sizes, int n_in,
                              void* d_out, int out_size)
{
    const float* q  = (const float*)d_in[0];
    const float* k  = (const float*)d_in[1];
    const float* W  = (const float*)d_in[2];
    const float* b  = (const float*)d_in[3];
    const float* Wd = (const float*)d_in[4];
    float* out = (float*)d_out;

    cudaFuncSetAttribute(score_mma_kernel,
                         cudaFuncAttributeMaxDynamicSharedMemorySize, SMEM_NEED);

    dim3 g1(16, BH + KCONV_BLKS_Y);
    prep_kernel<<<g1, 512>>>(q, k, W, Wd);

    dim3 g3(SV / 128, SV / 128, BH);
    score_mma_kernel<<<g3, 256, SMEM_NEED>>>(b, Wd, out);
}

// round 6
// speedup vs baseline: 2.7848x; 1.1546x over previous
#include <cuda_runtime.h>
#include <cuda_fp16.h>
#include <cstdint>
#include <cstddef>

// Problem constants
#define BV 4
#define HN 16
#define SV 1024
#define DV 64
#define BH (BV*HN)

// fp16 operands (device scratch; no allocation)
__device__ __half g_qhi[(size_t)BH * SV * DV];
__device__ __half g_khi[(size_t)BH * SV * DV];

__device__ __forceinline__ uint32_t smem_u32(const void* p) {
    uint32_t a;
    asm("{ .reg .u64 t; cvta.to.shared.u64 t, %1; cvt.u32.u64 %0, t; }" : "=r"(a) : "l"(p));
    return a;
}
__device__ __forceinline__ uint32_t sw128(uint32_t off) {
    return off ^ ((off >> 3) & 0x70);
}
__device__ __forceinline__ void ldsm_x4(uint32_t addr, uint32_t& r0, uint32_t& r1,
                                        uint32_t& r2, uint32_t& r3) {
    asm volatile("ldmatrix.sync.aligned.m8n8.x4.shared.b16 {%0,%1,%2,%3}, [%4];"
                 : "=r"(r0), "=r"(r1), "=r"(r2), "=r"(r3) : "r"(addr));
}
__device__ __forceinline__ void mma_f16(float* c, const uint32_t* a,
                                        uint32_t b0, uint32_t b1) {
    asm volatile(
        "mma.sync.aligned.m16n8k16.row.col.f32.f16.f16.f32 "
        "{%0,%1,%2,%3}, {%4,%5,%6,%7}, {%8,%9}, {%0,%1,%2,%3};"
        : "+f"(c[0]), "+f"(c[1]), "+f"(c[2]), "+f"(c[3])
        : "r"(a[0]), "r"(a[1]), "r"(a[2]), "r"(a[3]), "r"(b0), "r"(b1));
}

// ---------------------------------------------------------------------------
// Kernel 1 (fused prep grid):
//  y <  BH : fold via tensor cores: q'' = q @ M_h,  M_h = 32*I + Wd[h]*W[h]
//            (fp16 hi/lo 3-pass split -> fp32 acc -> near-exact), emit fp16.
//  y >= BH : convert k -> fp16 (g_khi)
// grid (8, BH+16), 256 threads.
// smem (fold): A_hi 16K | A_lo 16K | M_hi 8K | M_lo 8K  (+1K align)
// ---------------------------------------------------------------------------
#define PREP_SMEM (49152 + 1024)
__global__ __launch_bounds__(256, 2)
void prep_kernel(const float* __restrict__ q,
                 const float* __restrict__ k,
                 const float* __restrict__ W,
                 const float* __restrict__ Wd)
{
    const int t = threadIdx.x;

    if (blockIdx.y >= BH) {
        // ---- k -> fp16 conversion: 128 blocks, 8192 float4 each ----
        const int pb = (blockIdx.y - BH) * gridDim.x + blockIdx.x;   // 0..127
        const size_t base = (size_t)pb * 8192;
        __half2* ph = reinterpret_cast<__half2*>(g_khi);
        #pragma unroll
        for (int it = 0; it < 32; it++) {
            const size_t i = base + (size_t)it * 256 + t;
            float4 v = reinterpret_cast<const float4*>(k)[i];
            ph[2 * i]     = __floats2half2_rn(v.x, v.y);
            ph[2 * i + 1] = __floats2half2_rn(v.z, v.w);
        }
        return;
    }

    // ---- fold ----
    extern __shared__ char smem_raw[];
    const uint32_t smem_base = smem_u32(smem_raw);
    const uint32_t base_al   = (smem_base + 1023u) & ~1023u;
    char* tilec = smem_raw + (base_al - smem_base);
    const uint32_t Ah = base_al;               // 128 rows x 128B
    const uint32_t Al = base_al + 16384;
    const uint32_t Mh = base_al + 32768;       // 64 rows (e) x 128B (d)
    const uint32_t Ml = base_al + 40960;

    const int bh = blockIdx.y;
    const int h  = bh % HN;
    const int i0 = blockIdx.x * 128;

    const float* qb = q + (size_t)bh * SV * DV + (size_t)i0 * DV;
    const float* Wh = W + (size_t)h * DV * DV;
    const float  wd = Wd[h];

    // Build M = 32*I + wd*W, transposed into smem as [e][d], hi/lo split
    #pragma unroll
    for (int it = 0; it < 16; it++) {
        const int idx = t + it * 256;          // d*64+e
        const int d = idx >> 6, e = idx & 63;
        float val = wd * Wh[idx] + (d == e ? 32.0f : 0.0f);
        __half hi = __float2half(val);
        __half lo = __float2half(val - __half2float(hi));
        const uint32_t off = sw128((uint32_t)(e * 128 + d * 2));
        *reinterpret_cast<__half*>(tilec + (Mh - base_al) + off) = hi;
        *reinterpret_cast<__half*>(tilec + (Ml - base_al) + off) = lo;
    }

    // Load q tile (128 x 64 f32), split hi/lo into swizzled fp16 tiles
    #pragma unroll
    for (int it = 0; it < 4; it++) {
        const int idx = t + it * 256;          // 0..1023 chunks of 8 d-values
        const int row = idx >> 3;
        const int c8  = idx & 7;
        const float4 v0 = reinterpret_cast<const float4*>(qb + (size_t)row * DV)[c8 * 2];
        const float4 v1 = reinterpret_cast<const float4*>(qb + (size_t)row * DV)[c8 * 2 + 1];
        __half h0 = __float2half(v0.x), h1 = __float2half(v0.y);
        __half h2 = __float2half(v0.z), h3 = __float2half(v0.w);
        __half h4 = __float2half(v1.x), h5 = __float2half(v1.y);
        __half h6 = __float2half(v1.z), h7 = __float2half(v1.w);
        __half2 hv[4] = { __half2(h0,h1), __half2(h2,h3), __half2(h4,h5), __half2(h6,h7) };
        __half2 lv[4] = {
            __floats2half2_rn(v0.x - __half2float(h0), v0.y - __half2float(h1)),
            __floats2half2_rn(v0.z - __half2float(h2), v0.w - __half2float(h3)),
            __floats2half2_rn(v1.x - __half2float(h4), v1.y - __half2float(h5)),
            __floats2half2_rn(v1.z - __half2float(h6), v1.w - __half2float(h7)) };
        const uint32_t off = sw128((uint32_t)(row * 128 + c8 * 16));
        *reinterpret_cast<uint4*>(tilec + off)         = *reinterpret_cast<uint4*>(hv);
        *reinterpret_cast<uint4*>(tilec + 16384 + off) = *reinterpret_cast<uint4*>(lv);
    }
    __syncthreads();

    // Warp tile 32(M) x 32(N=e): warp grid 4 x 2
    const int wid  = t >> 5;
    const int lane = t & 31;
    const int m0w  = (wid & 3) * 32;
    const int n0w  = (wid >> 2) * 32;

    float acc[2][4][4];
    #pragma unroll
    for (int m = 0; m < 2; m++)
        #pragma unroll
        for (int n = 0; n < 4; n++)
            #pragma unroll
            for (int r = 0; r < 4; r++) acc[m][n][r] = 0.0f;

    const uint32_t a_row = lane & 15;
    const uint32_t a_ch  = (lane >> 4) << 4;
    const uint32_t b_row = (lane & 7) | ((lane >> 4) << 3);
    const uint32_t b_ch  = ((lane >> 3) & 1) << 4;

    #pragma unroll
    for (int kk = 0; kk < 4; kk++) {
        const uint32_t kb = (uint32_t)kk * 32;
        uint32_t ah[2][4], al[2][4];
        #pragma unroll
        for (int m = 0; m < 2; m++) {
            const uint32_t ro = sw128((uint32_t)(m0w + m * 16 + a_row) * 128 + kb + a_ch);
            ldsm_x4(Ah + ro, ah[m][0], ah[m][1], ah[m][2], ah[m][3]);
            ldsm_x4(Al + ro, al[m][0], al[m][1], al[m][2], al[m][3]);
        }
        uint32_t bh_f[4][2], bl_f[4][2];
        #pragma unroll
        for (int tn = 0; tn < 2; tn++) {
            const uint32_t ro = sw128((uint32_t)(n0w + tn * 16 + b_row) * 128 + kb + b_ch);
            ldsm_x4(Mh + ro, bh_f[2*tn][0], bh_f[2*tn][1], bh_f[2*tn+1][0], bh_f[2*tn+1][1]);
            ldsm_x4(Ml + ro, bl_f[2*tn][0], bl_f[2*tn][1], bl_f[2*tn+1][0], bl_f[2*tn+1][1]);
        }
        #pragma unroll
        for (int m = 0; m < 2; m++)
            #pragma unroll
            for (int n = 0; n < 4; n++) {
                mma_f16(acc[m][n], ah[m], bh_f[n][0], bh_f[n][1]);
                mma_f16(acc[m][n], ah[m], bl_f[n][0], bl_f[n][1]);
                mma_f16(acc[m][n], al[m], bh_f[n][0], bh_f[n][1]);
            }
    }

    // Epilogue: fp32 acc -> fp16 q'' (half2 stores)
    __half* oh = g_qhi + (size_t)bh * SV * DV;
    #pragma unroll
    for (int m = 0; m < 2; m++) {
        #pragma unroll
        for (int half = 0; half < 2; half++) {
            const int row = i0 + m0w + m * 16 + half * 8 + (lane >> 2);
            #pragma unroll
            for (int n = 0; n < 4; n++) {
                const int col = n0w + n * 8 + (lane & 3) * 2;
                __half2 v = __floats2half2_rn(acc[m][n][half * 2], acc[m][n][half * 2 + 1]);
                *reinterpret_cast<__half2*>(oh + (size_t)row * DV + col) = v;
            }
        }
    }
}

// ---------------------------------------------------------------------------
// Kernel 2: batched GEMM on HMMA, single pass fp16 -> f32.
//   out[bh][i][j] = q''_i · k_j + Wd[h]*b[h]
// 128(M) x 64(N) tile per CTA. grid (16, 8, 64) = 8192, 256 threads = 8 warps.
// Warp tile: 32 x 32. K=64 in smem, SW128-swizzled.
// ---------------------------------------------------------------------------
#define SC_SMEM (24576 + 1024)
__global__ __launch_bounds__(256, 3)
void score_mma_kernel(const float* __restrict__ b,
                      const float* __restrict__ Wd,
                      float* __restrict__ out)
{
    extern __shared__ char smem_raw[];
    const uint32_t smem_base = smem_u32(smem_raw);
    const uint32_t base_al   = (smem_base + 1023u) & ~1023u;
    char* tilec = smem_raw + (base_al - smem_base);
    const uint32_t Ab = base_al;            // 128 rows x 128B = 16K
    const uint32_t Bb = base_al + 16384;    // 64 rows x 128B  = 8K

    const int t    = threadIdx.x;
    const int wid  = t >> 5;
    const int lane = t & 31;
    const int bh   = blockIdx.z;
    const int h    = bh % HN;
    const int i0   = blockIdx.y * 128;
    const int j0   = blockIdx.x * 64;

    // ---- Load tiles into swizzled smem ----
    const size_t boff = (size_t)bh * SV * DV;
    const __half* qh = g_qhi + boff + (size_t)i0 * DV;
    const __half* kh = g_khi + boff + (size_t)j0 * DV;

    #pragma unroll
    for (int it = 0; it < 4; it++) {
        const int idx = t + it * 256;      // 0..1023
        const int row = idx >> 3;
        const int c16 = idx & 7;
        const uint32_t off = sw128((uint32_t)(row * 128 + c16 * 16));
        *reinterpret_cast<uint4*>(tilec + off) =
            reinterpret_cast<const uint4*>(qh + (size_t)row * DV)[c16];
    }
    #pragma unroll
    for (int it = 0; it < 2; it++) {
        const int idx = t + it * 256;      // 0..511
        const int row = idx >> 3;
        const int c16 = idx & 7;
        const uint32_t off = sw128((uint32_t)(row * 128 + c16 * 16));
        *reinterpret_cast<uint4*>(tilec + 16384 + off) =
            reinterpret_cast<const uint4*>(kh + (size_t)row * DV)[c16];
    }
    __syncthreads();

    // ---- Warp tile 32x32: warp grid 4(M) x 2(N) ----
    const int m0w = (wid & 3) * 32;
    const int n0w = (wid >> 2) * 32;

    float acc[2][4][4];
    #pragma unroll
    for (int m = 0; m < 2; m++)
        #pragma unroll
        for (int n = 0; n < 4; n++)
            #pragma unroll
            for (int r = 0; r < 4; r++) acc[m][n][r] = 0.0f;

    const uint32_t a_row = lane & 15;
    const uint32_t a_ch  = (lane >> 4) << 4;
    const uint32_t b_row = (lane & 7) | ((lane >> 4) << 3);
    const uint32_t b_ch  = ((lane >> 3) & 1) << 4;

    #pragma unroll
    for (int kk = 0; kk < 4; kk++) {
        const uint32_t kb = (uint32_t)kk * 32;
        uint32_t a[2][4];
        #pragma unroll
        for (int m = 0; m < 2; m++) {
            const uint32_t ro = sw128((uint32_t)(m0w + m * 16 + a_row) * 128 + kb + a_ch);
            ldsm_x4(Ab + ro, a[m][0], a[m][1], a[m][2], a[m][3]);
        }
        uint32_t bf[4][2];
        #pragma unroll
        for (int tn = 0; tn < 2; tn++) {
            const uint32_t ro = sw128((uint32_t)(n0w + tn * 16 + b_row) * 128 + kb + b_ch);
            ldsm_x4(Bb + ro, bf[2*tn][0], bf[2*tn][1], bf[2*tn+1][0], bf[2*tn+1][1]);
        }
        #pragma unroll
        for (int m = 0; m < 2; m++)
            #pragma unroll
            for (int n = 0; n < 4; n++)
                mma_f16(acc[m][n], a[m], bf[n][0], bf[n][1]);
    }

    // ---- Epilogue: add bias, float2 stores ----
    const float cbias = Wd[h] * b[h];
    float* ob = out + (size_t)bh * SV * SV;
    const int row_base = i0 + m0w + (lane >> 2);
    const int col_base = j0 + n0w + (lane & 3) * 2;

    #pragma unroll
    for (int m = 0; m < 2; m++) {
        #pragma unroll
        for (int half = 0; half < 2; half++) {
            const int r = row_base + m * 16 + half * 8;
            float* prow = ob + (size_t)r * SV + col_base;
            #pragma unroll
            for (int n = 0; n < 4; n++) {
                float2 v;
                v.x = acc[m][n][half * 2 + 0] + cbias;
                v.y = acc[m][n][half * 2 + 1] + cbias;
                *reinterpret_cast<float2*>(prow + n * 8) = v;
            }
        }
    }
}

// ---------------------------------------------------------------------------
extern "C" void kernel_launch(void* const* d_in, const int* in_sizes, int n_in,
                              void* d_out, int out_size)
{
    const float* q  = (const float*)d_in[0];
    const float* k  = (const float*)d_in[1];
    const float* W  = (const float*)d_in[2];
    const float* b  = (const float*)d_in[3];
    const float* Wd = (const float*)d_in[4];
    float* out = (float*)d_out;

    cudaFuncSetAttribute(prep_kernel,
                         cudaFuncAttributeMaxDynamicSharedMemorySize, PREP_SMEM);
    cudaFuncSetAttribute(score_mma_kernel,
                         cudaFuncAttributeMaxDynamicSharedMemorySize, SC_SMEM);

    dim3 g1(8, BH + 16);
    prep_kernel<<<g1, 256, PREP_SMEM>>>(q, k, W, Wd);

    dim3 g3(SV / 64, SV / 128, BH);
    score_mma_kernel<<<g3, 256, SC_SMEM>>>(b, Wd, out);
}